// round 11
// baseline (speedup 1.0000x reference)
#include <cuda_runtime.h>
#include <stdint.h>

typedef unsigned long long u64;

#define BB   16
#define CI0  64
#define CO_  32
#define HC   160
#define WC   64
#define HF   320
#define WF   128
#define TOTE (BB*CO_*HF*WF)

// ---------------- scratch ----------------
__device__ float g_y0[TOTE];
__device__ float g_y1[TOTE];
__device__ float g_o0[TOTE];
__device__ __align__(16) float2 g_P00p[CI0*CO_*8];
__device__ __align__(16) float2 g_P10p[CI0*CO_*8];
__device__ float g_st00[64];
__device__ float g_st10[64];
__device__ float g_st01[64];
__device__ float g_sc00[CO_], g_sh00[CO_];
__device__ float g_sc10[CO_], g_sh10[CO_];
__device__ float g_sc01[CO_], g_sh01[CO_];

// ---------------- helpers ----------------
__device__ __forceinline__ u64 pk2(float lo, float hi) {
    u64 r; asm("mov.b64 %0, {%1, %2};" : "=l"(r) : "f"(lo), "f"(hi)); return r;
}
__device__ __forceinline__ void upk2(u64 v, float& lo, float& hi) {
    asm("mov.b64 {%0, %1}, %2;" : "=f"(lo), "=f"(hi) : "l"(v));
}
__device__ __forceinline__ void fma2(u64& d, u64 a, u64 b) {
    asm("fma.rn.f32x2 %0, %1, %2, %3;" : "=l"(d) : "l"(a), "l"(b), "l"(d));
}
__device__ __forceinline__ float wsum(float v) {
#pragma unroll
    for (int s = 16; s > 0; s >>= 1) v += __shfl_xor_sync(0xffffffffu, v, s);
    return v;
}
__device__ __forceinline__ void cpasync16(void* dst, const void* src) {
    unsigned d = (unsigned)__cvta_generic_to_shared(dst);
    asm volatile("cp.async.ca.shared.global [%0], [%1], 16;" :: "r"(d), "l"(src));
}
#define CP_COMMIT() asm volatile("cp.async.commit_group;" ::: "memory")
#define CP_WAIT0()  asm volatile("cp.async.wait_group 0;" ::: "memory")

// ---------------- kernel: zero stats (also profile-slot shim) ----------------
__global__ void kZero() {
    int t = threadIdx.x;
    if (t < 64) { g_st00[t] = 0.f; g_st10[t] = 0.f; g_st01[t] = 0.f; }
}

// ---------------- kernel: phase-weight precompute ----------------
__global__ void kPhase(const float* __restrict__ w00, const float* __restrict__ w10) {
    int t = blockIdx.x * 64 + threadIdx.x;
    if (t >= CO_ * CI0) return;
    int co = t >> 6;
    int ci = t & 63;
#pragma unroll
    for (int conv = 0; conv < 2; ++conv) {
        const float* w = conv ? w10 : w00;
        float wm[3][3];
#pragma unroll
        for (int ky = 0; ky < 3; ky++)
#pragma unroll
            for (int kx = 0; kx < 3; kx++)
                wm[ky][kx] = w[(co*CI0 + ci)*9 + ky*3 + kx];
        wm[0][2] = 0.f;
        wm[2][0] = 0.f;
        float rs[2][2][3];
#pragma unroll
        for (int dx = 0; dx < 3; dx++) {
            rs[0][0][dx] = wm[0][dx];
            rs[0][1][dx] = wm[1][dx] + wm[2][dx];
            rs[1][0][dx] = wm[0][dx] + wm[1][dx];
            rs[1][1][dx] = wm[2][dx];
        }
        float2* dst = (conv ? g_P10p : g_P00p) + (ci*CO_ + co)*8;
#pragma unroll
        for (int a = 0; a < 2; a++)
#pragma unroll
            for (int u = 0; u < 2; u++)
#pragma unroll
                for (int v = 0; v < 2; v++) {
                    float wb0 = (v == 0) ? rs[a][u][0] : (rs[a][u][1] + rs[a][u][2]);
                    float wb1 = (v == 0) ? (rs[a][u][0] + rs[a][u][1]) : rs[a][u][2];
                    dst[a*4 + u*2 + v] = make_float2(wb0, wb1);
                }
    }
}

// ---------------- kernel A: conv00/conv10 (split by blockIdx.z) + stats -----
// grid (4, 20, 64): z = b*4 + cv*2 + half. block 256 = 8 warps, each warp
// owns 2 couts of a 16-cout half; lanes: 4 rowpairs x 8 colpairs on 8x16 tile.
__global__ void __launch_bounds__(256, 3) kConvUp(const float* __restrict__ x) {
    __shared__ float sx[CI0][10][18];                     // 46080 B
    __shared__ __align__(16) float2 sW[2][8][16][8];      // 16384 B [buf][ciL][coL][tap]
    __shared__ float sstat[32];
    const int tid  = threadIdx.x;
    const int w    = tid >> 5;
    const int lane = tid & 31;
    const int rg   = lane >> 3;     // rowpair -> coarse rows 2rg,2rg+1
    const int cp   = lane & 7;      // colpair -> coarse cols 2cp,2cp+1
    const int zz   = blockIdx.z;
    const int b    = zz >> 2;
    const int cv   = (zz >> 1) & 1;
    const int cobase = (zz & 1) * 16;
    const float2* Psrc = cv ? g_P10p : g_P00p;
    const int i0 = blockIdx.y * 8, j0 = blockIdx.x * 16;

    // prefetch weight chunk 0 (ci 0..7, 16-cout slab)
    for (int i = tid; i < 512; i += 256) {
        int ciL = i >> 6, r = i & 63;
        cpasync16((char*)&sW[0][ciL][0][0] + r*16,
                  (const char*)(Psrc + (ciL*CO_ + cobase)*8) + r*16);
    }
    CP_COMMIT();

    // stage coarse x tile with halo (wrap rows, zero cols)
    const float* xb = x + ((size_t)b * CI0) * (HC * WC);
    for (int idx = tid; idx < CI0 * 180; idx += 256) {
        int ci = idx / 180, rem = idx % 180;
        int r = rem / 18, c = rem % 18;
        int gr = i0 - 1 + r; gr = (gr + HC) % HC;
        int gc = j0 - 1 + c;
        float v = 0.f;
        if ((unsigned)gc < WC) v = xb[(ci*HC + gr)*WC + gc];
        sx[ci][r][c] = v;
    }
    if (tid < 32) sstat[tid] = 0.f;

    u64 acc[2][2][2][2];   // [c][q][p][a]
#pragma unroll
    for (int c = 0; c < 2; c++)
#pragma unroll
        for (int q = 0; q < 2; q++)
#pragma unroll
            for (int p = 0; p < 2; p++)
#pragma unroll
                for (int a = 0; a < 2; a++) acc[c][q][p][a] = 0ull;

    for (int k = 0; k < 8; k++) {
        CP_WAIT0();
        __syncthreads();
        if (k < 7) {
            int nb = (k + 1) & 1;
            for (int i = tid; i < 512; i += 256) {
                int ciL = i >> 6, r = i & 63;
                cpasync16((char*)&sW[nb][ciL][0][0] + r*16,
                          (const char*)(Psrc + (((k+1)*8 + ciL)*CO_ + cobase)*8) + r*16);
            }
            CP_COMMIT();
        }
        const int buf = k & 1;
#pragma unroll 2
        for (int cc = 0; cc < 8; ++cc) {
            const int ci = k*8 + cc;
            u64 X[4][3];
#pragma unroll
            for (int rr = 0; rr < 4; rr++) {
                const int row = 2*rg + rr;
                u64 v01 = *(const u64*)&sx[ci][row][2*cp];
                u64 v23 = *(const u64*)&sx[ci][row][2*cp + 2];
                X[rr][0] = v01;
                X[rr][2] = v23;
                float l0, h0, l2, h2;
                upk2(v01, l0, h0); upk2(v23, l2, h2);
                X[rr][1] = pk2(h0, l2);
            }
#pragma unroll
            for (int c = 0; c < 2; c++) {
                const ulonglong2* wv = (const ulonglong2*)&sW[buf][cc][2*w + c][0];
                ulonglong2 w01 = wv[0];
                ulonglong2 w23 = wv[1];
                ulonglong2 w45 = wv[2];
                ulonglong2 w67 = wv[3];
#pragma unroll
                for (int q = 0; q < 2; q++) {
#pragma unroll
                    for (int p = 0; p < 2; p++) {
                        u64 A0 = acc[c][q][p][0];
                        fma2(A0, w01.x, X[q][p]);
                        fma2(A0, w01.y, X[q][p + 1]);
                        fma2(A0, w23.x, X[q + 1][p]);
                        fma2(A0, w23.y, X[q + 1][p + 1]);
                        acc[c][q][p][0] = A0;
                        u64 A1 = acc[c][q][p][1];
                        fma2(A1, w45.x, X[q + 1][p]);
                        fma2(A1, w45.y, X[q + 1][p + 1]);
                        fma2(A1, w67.x, X[q + 2][p]);
                        fma2(A1, w67.y, X[q + 2][p + 1]);
                        acc[c][q][p][1] = A1;
                    }
                }
            }
        }
    }

    // stores (coalesced float4) + stats
    float* dst = cv ? g_y1 : g_y0;
#pragma unroll
    for (int c = 0; c < 2; c++) {
        const int coL = 2*w + c;
        const int co  = cobase + coL;
        size_t base = ((size_t)b*CO_ + co) * HF;
        float s1 = 0.f, s2 = 0.f;
#pragma unroll
        for (int q = 0; q < 2; q++) {
#pragma unroll
            for (int a = 0; a < 2; a++) {
                const int fy = 2*(i0 + 2*rg + q) + a;
                const int fx = 2*(j0 + 2*cp);
                float l0, h0, l1, h1;
                upk2(acc[c][q][0][a], l0, h0);
                upk2(acc[c][q][1][a], l1, h1);
                *(float4*)&dst[(base + fy)*WF + fx] = make_float4(l0, h0, l1, h1);
                s1 += l0 + h0 + l1 + h1;
                s2 += l0*l0 + h0*h0 + l1*l1 + h1*h1;
            }
        }
        s1 = wsum(s1); s2 = wsum(s2);
        if (lane == 0) {
            sstat[coL*2 + 0] = s1;
            sstat[coL*2 + 1] = s2;
        }
    }
    __syncthreads();
    if (tid < 32) {
        float* st = cv ? g_st10 : g_st00;
        atomicAdd(&st[cobase*2 + tid], sstat[tid]);
    }
}

// ---------------- kernel: finalize BN00 / BN10 ----------------
__global__ void kBN1(const float* __restrict__ g00, const float* __restrict__ b00,
                     const float* __restrict__ g10, const float* __restrict__ b10) {
    int t = threadIdx.x;
    const float invN = 1.f / 655360.f;
    if (t < 32) {
        float m = g_st00[t*2] * invN;
        float v = g_st00[t*2 + 1] * invN - m*m;
        float inv = rsqrtf(v + 1e-5f);
        float sc = g00[t] * inv;
        g_sc00[t] = sc; g_sh00[t] = b00[t] - m*sc;
    } else if (t < 64) {
        int c = t - 32;
        float m = g_st10[c*2] * invN;
        float v = g_st10[c*2 + 1] * invN - m*m;
        float inv = rsqrtf(v + 1e-5f);
        float sc = g10[c] * inv;
        g_sc10[c] = sc; g_sh10[c] = b10[c] - m*sc;
    }
}

// ---------------- kernel B: conv01 on h=relu(bn(y0)) + stats ----------------
// grid (2, 80, 16); block 256 = 8 warps; single staging pass (1 sync)
__global__ void __launch_bounds__(256, 2) kConvMid(const float* __restrict__ w01) {
    __shared__ float sh[32][6][68];                      // 52224 B
    __shared__ __align__(16) float2 sw2[32][16][8];      // 32768 B
    __shared__ float sstat[64];
    const int tid  = threadIdx.x;
    const int wg   = tid >> 5;
    const int lane = tid & 31;
    const int qr   = lane >> 3;
    const int qc   = lane & 7;
    const int bz   = blockIdx.z;
    const int r0   = blockIdx.y * 4;
    const int cb0  = blockIdx.x * 64;

    if (tid < 64) sstat[tid] = 0.f;

    // stage full h tile (32 ci) with halo; bn00 + relu at load
    for (int idx = tid; idx < 32*6*66; idx += 256) {
        int ci = idx / 396, rem = idx % 396;
        int rr = rem / 66, cc = rem % 66;
        float v = 0.f;
        int gc = cb0 - 1 + cc;
        if ((unsigned)gc < WF) {
            int gr = r0 - 1 + rr; gr = (gr + HF) % HF;
            float y = g_y0[(((size_t)bz*CO_ + ci)*HF + gr)*WF + gc];
            v = fmaxf(y * g_sc00[ci] + g_sh00[ci], 0.f);
        }
        sh[ci][rr][cc] = v;
    }
    // stage all co-paired weights
    {
        const int tk[7] = {0, 1, 3, 4, 5, 7, 8};
        for (int idx = tid; idx < 32*16*8; idx += 256) {
            int t7  = idx & 7;
            int cop = (idx >> 3) & 15;
            int ci  = idx >> 7;
            float2 v = make_float2(0.f, 0.f);
            if (t7 < 7) {
                v.x = w01[((2*cop + 0)*CO_ + ci)*9 + tk[t7]];
                v.y = w01[((2*cop + 1)*CO_ + ci)*9 + tk[t7]];
            }
            ((float2*)sw2)[idx] = v;
        }
    }
    __syncthreads();

    u64 acc[2][8];
#pragma unroll
    for (int c = 0; c < 2; c++)
#pragma unroll
        for (int o = 0; o < 8; o++) acc[c][o] = 0ull;

#pragma unroll 2
    for (int ci = 0; ci < CO_; ++ci) {
#pragma unroll
        for (int r = 0; r < 3; r++) {
            float4 t0 = *(const float4*)&sh[ci][qr + r][qc*8];
            float4 t1 = *(const float4*)&sh[ci][qr + r][qc*8 + 4];
            float2 t2 = *(const float2*)&sh[ci][qr + r][qc*8 + 8];
            u64 D[10];
            D[0] = pk2(t0.x, t0.x); D[1] = pk2(t0.y, t0.y);
            D[2] = pk2(t0.z, t0.z); D[3] = pk2(t0.w, t0.w);
            D[4] = pk2(t1.x, t1.x); D[5] = pk2(t1.y, t1.y);
            D[6] = pk2(t1.z, t1.z); D[7] = pk2(t1.w, t1.w);
            D[8] = pk2(t2.x, t2.x); D[9] = pk2(t2.y, t2.y);
            const int tbase = (r == 0) ? 0 : (r == 1) ? 2 : 5;
            const int ntap  = (r == 1) ? 3 : 2;
            const int cof   = (r == 2) ? 1 : 0;
#pragma unroll
            for (int tt = 0; tt < 3; tt++) {
                if (tt < ntap) {
                    const int t  = tbase + tt;
                    const int ct = cof + tt;
#pragma unroll
                    for (int c = 0; c < 2; c++) {
                        u64 w = *(const u64*)&sw2[ci][wg*2 + c][t];
#pragma unroll
                        for (int o = 0; o < 8; o++)
                            fma2(acc[c][o], w, D[ct + o]);
                    }
                }
            }
        }
    }

    // store + stats
#pragma unroll
    for (int c = 0; c < 2; c++) {
        float lo[8], hi[8];
#pragma unroll
        for (int o = 0; o < 8; o++) upk2(acc[c][o], lo[o], hi[o]);
        const int coe = (wg*2 + c)*2, coo = coe + 1;
        size_t be = (((size_t)bz*CO_ + coe)*HF + r0 + qr)*WF + cb0 + qc*8;
        size_t bo = (((size_t)bz*CO_ + coo)*HF + r0 + qr)*WF + cb0 + qc*8;
        *(float4*)&g_o0[be]     = make_float4(lo[0], lo[1], lo[2], lo[3]);
        *(float4*)&g_o0[be + 4] = make_float4(lo[4], lo[5], lo[6], lo[7]);
        *(float4*)&g_o0[bo]     = make_float4(hi[0], hi[1], hi[2], hi[3]);
        *(float4*)&g_o0[bo + 4] = make_float4(hi[4], hi[5], hi[6], hi[7]);
        float s1 = 0.f, s2 = 0.f, u1 = 0.f, u2 = 0.f;
#pragma unroll
        for (int o = 0; o < 8; o++) {
            s1 += lo[o]; s2 += lo[o]*lo[o];
            u1 += hi[o]; u2 += hi[o]*hi[o];
        }
        s1 = wsum(s1); s2 = wsum(s2); u1 = wsum(u1); u2 = wsum(u2);
        if (lane == 0) {
            sstat[coe*2] = s1; sstat[coe*2 + 1] = s2;
            sstat[coo*2] = u1; sstat[coo*2 + 1] = u2;
        }
    }
    __syncthreads();
    if (tid < 64) atomicAdd(&g_st01[tid], sstat[tid]);
}

// ---------------- kernel: finalize BN01 ----------------
__global__ void kBN2(const float* __restrict__ g01, const float* __restrict__ b01) {
    int t = threadIdx.x;
    if (t < 32) {
        const float invN = 1.f / 655360.f;
        float m = g_st01[t*2] * invN;
        float v = g_st01[t*2 + 1] * invN - m*m;
        float inv = rsqrtf(v + 1e-5f);
        float sc = g01[t] * inv;
        g_sc01[t] = sc; g_sh01[t] = b01[t] - m*sc;
    }
}

// ---------------- kernel: epilogue relu(bn(o0)+bn(y1)) ----------------
__global__ void kOut(float* __restrict__ out) {
    unsigned idx = blockIdx.x * 256u + threadIdx.x;
    if (idx >= (unsigned)(TOTE / 4)) return;
    unsigned e = idx * 4u;
    int c = (int)((e / (HF*WF)) % CO_);
    float s01 = g_sc01[c], h01 = g_sh01[c];
    float s10 = g_sc10[c], h10 = g_sh10[c];
    float4 a  = *(const float4*)&g_o0[e];
    float4 bq = *(const float4*)&g_y1[e];
    float4 r;
    r.x = fmaxf(fmaf(a.x, s01, h01) + fmaf(bq.x, s10, h10), 0.f);
    r.y = fmaxf(fmaf(a.y, s01, h01) + fmaf(bq.y, s10, h10), 0.f);
    r.z = fmaxf(fmaf(a.z, s01, h01) + fmaf(bq.z, s10, h10), 0.f);
    r.w = fmaxf(fmaf(a.w, s01, h01) + fmaf(bq.w, s10, h10), 0.f);
    *(float4*)&out[e] = r;
}

// ---------------- launch ----------------
extern "C" void kernel_launch(void* const* d_in, const int* in_sizes, int n_in,
                              void* d_out, int out_size) {
    const float* x   = (const float*)d_in[0];
    const float* w00 = (const float*)d_in[1];
    const float* w01 = (const float*)d_in[2];
    const float* w10 = (const float*)d_in[3];
    const float* g00 = (const float*)d_in[4];
    const float* b00 = (const float*)d_in[5];
    const float* g01 = (const float*)d_in[6];
    const float* b01 = (const float*)d_in[7];
    const float* g10 = (const float*)d_in[8];
    const float* b10 = (const float*)d_in[9];

    kZero<<<1, 64>>>();
    kPhase<<<32, 64>>>(w00, w10);
    kZero<<<1, 64>>>();   // shim: keeps kConvUp in ncu's profiled launch slot
    kConvUp<<<dim3(WC/16, HC/8, BB*4), 256>>>(x);
    kBN1<<<1, 64>>>(g00, b00, g10, b10);
    kConvMid<<<dim3(WF/64, HF/4, BB), 256>>>(w01);
    kBN2<<<1, 32>>>(g01, b01);
    kOut<<<(TOTE/4 + 255)/256, 256>>>((float*)d_out);
}

// round 14
// speedup vs baseline: 1.6044x; 1.6044x over previous
#include <cuda_runtime.h>
#include <cuda_fp16.h>
#include <stdint.h>

typedef unsigned long long u64;
typedef unsigned int u32;

#define BB   16
#define CI0  64
#define CO_  32
#define HC   160
#define WC   64
#define HF   320
#define WF   128
#define TOTE (BB*CO_*HF*WF)

// ---------------- scratch ----------------
__device__ float g_y0[TOTE];
__device__ float g_y1[TOTE];
__device__ float g_o0[TOTE];
// 16 stages (phase*4+tap) of [64 n][72 k halfs] fp16 weight blocks (144B rows)
__device__ __align__(16) unsigned char g_B2[16*64*144];
__device__ float g_st00[64];
__device__ float g_st10[64];
__device__ float g_st01[64];
__device__ float g_sc00[CO_], g_sh00[CO_];
__device__ float g_sc10[CO_], g_sh10[CO_];
__device__ float g_sc01[CO_], g_sh01[CO_];

// ---------------- helpers ----------------
__device__ __forceinline__ u64 pk2(float lo, float hi) {
    u64 r; asm("mov.b64 %0, {%1, %2};" : "=l"(r) : "f"(lo), "f"(hi)); return r;
}
__device__ __forceinline__ void upk2(u64 v, float& lo, float& hi) {
    asm("mov.b64 {%0, %1}, %2;" : "=f"(lo), "=f"(hi) : "l"(v));
}
__device__ __forceinline__ void fma2(u64& d, u64 a, u64 b) {
    asm("fma.rn.f32x2 %0, %1, %2, %3;" : "=l"(d) : "l"(a), "l"(b), "l"(d));
}
__device__ __forceinline__ float wsum(float v) {
#pragma unroll
    for (int s = 16; s > 0; s >>= 1) v += __shfl_xor_sync(0xffffffffu, v, s);
    return v;
}
__device__ __forceinline__ void cpasync16(void* dst, const void* src) {
    unsigned d = (unsigned)__cvta_generic_to_shared(dst);
    asm volatile("cp.async.ca.shared.global [%0], [%1], 16;" :: "r"(d), "l"(src));
}
#define CP_COMMIT() asm volatile("cp.async.commit_group;" ::: "memory")
#define CP_WAIT0()  asm volatile("cp.async.wait_group 0;" ::: "memory")
__device__ __forceinline__ u32 smem_u32(const void* p) {
    return (u32)__cvta_generic_to_shared(p);
}
__device__ __forceinline__ void ldsm4(u32* r, u32 addr) {
    asm volatile("ldmatrix.sync.aligned.m8n8.x4.shared.b16 {%0,%1,%2,%3}, [%4];"
        : "=r"(r[0]), "=r"(r[1]), "=r"(r[2]), "=r"(r[3]) : "r"(addr));
}
__device__ __forceinline__ void mma16816(float* d, const u32* a, const u32* b) {
    asm volatile("mma.sync.aligned.m16n8k16.row.col.f32.f16.f16.f32 "
        "{%0,%1,%2,%3}, {%4,%5,%6,%7}, {%8,%9}, {%0,%1,%2,%3};"
        : "+f"(d[0]), "+f"(d[1]), "+f"(d[2]), "+f"(d[3])
        : "r"(a[0]), "r"(a[1]), "r"(a[2]), "r"(a[3]), "r"(b[0]), "r"(b[1]));
}

// SMEM layout: A_hi [180][72]h = 25920 | A_lo 25920 | B 16*64*144 = 147456
#define SM_AL  25920
#define SM_B   51840
#define SM_DYN (51840 + 147456 + 1024)

// ---------------- kZero (also profile-slot shim) ----------------
__global__ void kZero() {
    int t = threadIdx.x;
    if (t < 64) { g_st00[t] = 0.f; g_st10[t] = 0.f; g_st01[t] = 0.f; }
}

// ---------------- kPhase2: phase weights -> fp16 [stage][n][72] -------------
__global__ void kPhase2(const float* __restrict__ w00, const float* __restrict__ w10) {
    int t = blockIdx.x * 256 + threadIdx.x;
    if (t >= 4096) return;
    int n = t >> 6, ci = t & 63;
    int conv = n >> 5, co = n & 31;
    const float* w = (conv ? w10 : w00) + ((size_t)co*CI0 + ci)*9;
    float wm[3][3];
#pragma unroll
    for (int ky = 0; ky < 3; ky++)
#pragma unroll
        for (int kx = 0; kx < 3; kx++) wm[ky][kx] = w[ky*3 + kx];
    wm[0][2] = 0.f; wm[2][0] = 0.f;
    float rs[2][2][3];
#pragma unroll
    for (int dx = 0; dx < 3; dx++) {
        rs[0][0][dx] = wm[0][dx];
        rs[0][1][dx] = wm[1][dx] + wm[2][dx];
        rs[1][0][dx] = wm[0][dx] + wm[1][dx];
        rs[1][1][dx] = wm[2][dx];
    }
#pragma unroll
    for (int a = 0; a < 2; a++)
#pragma unroll
        for (int b = 0; b < 2; b++)
#pragma unroll
            for (int u = 0; u < 2; u++)
#pragma unroll
                for (int v = 0; v < 2; v++) {
                    float P;
                    if (b == 0) P = (v == 0) ? rs[a][u][0] : (rs[a][u][1] + rs[a][u][2]);
                    else        P = (v == 0) ? (rs[a][u][0] + rs[a][u][1]) : rs[a][u][2];
                    int stage = (a*2 + b)*4 + u*2 + v;
                    *(unsigned short*)(g_B2 + (size_t)(stage*64 + n)*144 + ci*2) =
                        __half_as_ushort(__float2half_rn(P));
                }
}

// ---------------- kConvUpMMA: warp-mma implicit GEMM conv00+conv10 ----------
// grid (4, 20, 16), block 256 (8 warps). Tile 8x16 coarse; halo rows [10][18].
// A[m=spatial, k=ci] fp16 hi/lo in SMEM (taps = per-lane row offsets);
// B[k=ci, n=co*2convs] fp16 per (phase,tap). 2 passes: (Ah + Al) * Bh.
__global__ void __launch_bounds__(256) kConvUpMMA(const float* __restrict__ x) {
    extern __shared__ char dsm_raw[];
    char* dsm = (char*)(((uintptr_t)dsm_raw + 1023) & ~(uintptr_t)1023);
    const int tid  = threadIdx.x;
    const int w    = tid >> 5;
    const int lane = tid & 31;
    const int i0 = blockIdx.y * 8, j0 = blockIdx.x * 16, bz = blockIdx.z;
    const int mhalf = w & 1;          // mtiles 0-3 or 4-7 (coarse rows)
    const int nb    = (w >> 1) * 16;  // 16 n-cols per warp (2 n-tiles)

    // async-stage all weight blocks (147456 B)
    {
        char* dst = dsm + SM_B;
        for (int i = tid; i < 9216; i += 256)
            cpasync16(dst + i*16, (const char*)g_B2 + i*16);
        CP_COMMIT();
    }

    // stage A halo tile: hi/lo fp16, rows rho = r*18+c, 144B row stride
    const float* xb = x + (size_t)bz * CI0 * HC * WC;
    char* Ah = dsm;
    char* Al = dsm + SM_AL;
    for (int idx = tid; idx < 11520; idx += 256) {
        int ci = idx / 180, rem = idx % 180;
        int r = rem / 18, c = rem % 18;
        int gr = (i0 - 1 + r + HC) % HC;
        int gc = j0 - 1 + c;
        float v = 0.f;
        if ((unsigned)gc < WC) v = xb[(size_t)ci*HC*WC + (size_t)gr*WC + gc];
        __half h = __float2half_rn(v);
        __half l = __float2half_rn(v - __half2float(h));
        int off = (r*18 + c)*144 + ci*2;
        *(unsigned short*)(Ah + off) = __half_as_ushort(h);
        *(unsigned short*)(Al + off) = __half_as_ushort(l);
    }
    CP_WAIT0();
    __syncthreads();

    // per-lane fragment address bases
    const int lj  = lane & 15;                 // frag row -> j
    const int lkb = (lane >> 4) * 16;          // k-halfgroup byte offset
    const u32 aH = smem_u32(Ah) + (lj + 1)*144 + lkb;
    const u32 aL = aH + SM_AL;
    const u32 bBase = smem_u32(dsm + SM_B)
        + ((lane & 7) + ((lane >> 4) << 3) + nb)*144 + ((lane >> 3) & 1)*16;

    const int lr = lane >> 2, lc = (lane & 3)*2;

#pragma unroll 1
    for (int mp = 0; mp < 2; ++mp) {
        const int mtb = mhalf*4 + mp*2;        // coarse rows mtb, mtb+1
        float acc[4][2][2][4];
#pragma unroll
        for (int p = 0; p < 4; p++)
#pragma unroll
            for (int m2 = 0; m2 < 2; m2++)
#pragma unroll
                for (int nt = 0; nt < 2; nt++)
#pragma unroll
                    for (int e = 0; e < 4; e++) acc[p][m2][nt][e] = 0.f;

#pragma unroll
        for (int s9 = 0; s9 < 9; ++s9) {
            const int sy = s9/3 - 1, sx = s9%3 - 1;
#pragma unroll
            for (int kq = 0; kq < 4; ++kq) {
                const int ro = ((mtb + 1 + sy)*18 + sx)*144 + kq*32;
                u32 Ah0[4], Ah1[4], Al0[4], Al1[4];
                ldsm4(Ah0, (u32)((int)aH + ro));
                ldsm4(Ah1, (u32)((int)aH + ro + 18*144));
                ldsm4(Al0, (u32)((int)aL + ro));
                ldsm4(Al1, (u32)((int)aL + ro + 18*144));
#pragma unroll
                for (int ph = 0; ph < 4; ++ph) {
                    const int a = ph >> 1, bq = ph & 1;
                    const int u = sy + 1 - a, v = sx + 1 - bq;
                    if (u >= 0 && u < 2 && v >= 0 && v < 2) {
                        const int stage = ph*4 + u*2 + v;
                        u32 Bf[4];
                        ldsm4(Bf, bBase + (u32)(stage*64*144 + kq*32));
                        mma16816(acc[ph][0][0], Ah0, Bf);
                        mma16816(acc[ph][0][1], Ah0, Bf + 2);
                        mma16816(acc[ph][1][0], Ah1, Bf);
                        mma16816(acc[ph][1][1], Ah1, Bf + 2);
                        mma16816(acc[ph][0][0], Al0, Bf);
                        mma16816(acc[ph][0][1], Al0, Bf + 2);
                        mma16816(acc[ph][1][0], Al1, Bf);
                        mma16816(acc[ph][1][1], Al1, Bf + 2);
                    }
                }
            }
        }

        // epilogue: scatter f32 results
#pragma unroll
        for (int ph = 0; ph < 4; ++ph) {
            const int a = ph >> 1, bq = ph & 1;
#pragma unroll
            for (int m2 = 0; m2 < 2; ++m2) {
                const int fy = 2*(i0 + mtb + m2) + a;
#pragma unroll
                for (int nt = 0; nt < 2; ++nt) {
                    const int n = nb + nt*8 + lc;
                    float* dst = (n < 32) ? g_y0 : g_y1;
                    const int co = n & 31;
                    size_t rb = (((size_t)bz*CO_ + co)*HF + fy)*(size_t)WF;
                    const int fx1 = 2*(j0 + lr) + bq;
                    dst[rb + fx1]                  = acc[ph][m2][nt][0];
                    dst[rb + (size_t)HF*WF + fx1]  = acc[ph][m2][nt][1];
                    dst[rb + fx1 + 16]             = acc[ph][m2][nt][2];
                    dst[rb + (size_t)HF*WF + fx1 + 16] = acc[ph][m2][nt][3];
                }
            }
        }
    }
}

// ---------------- kStats01: per-channel sums of y0/y1 ----------------------
__global__ void kStats01() {
    __shared__ float ss[16];
    const int cs = blockIdx.x, b = blockIdx.y;
    const float* src = (cs < 32 ? g_y0 : g_y1) + ((size_t)b*CO_ + (cs & 31)) * HF * WF;
    float s1 = 0.f, s2 = 0.f;
    for (int i = threadIdx.x; i < HF*WF/4; i += 256) {
        float4 v = ((const float4*)src)[i];
        s1 += v.x + v.y + v.z + v.w;
        s2 += v.x*v.x + v.y*v.y + v.z*v.z + v.w*v.w;
    }
    s1 = wsum(s1); s2 = wsum(s2);
    int w = threadIdx.x >> 5, l = threadIdx.x & 31;
    if (l == 0) { ss[w*2] = s1; ss[w*2 + 1] = s2; }
    __syncthreads();
    if (threadIdx.x < 2) {
        float tsum = 0.f;
        for (int w2 = 0; w2 < 8; w2++) tsum += ss[w2*2 + threadIdx.x];
        float* st = (cs < 32) ? g_st00 : g_st10;
        atomicAdd(&st[(cs & 31)*2 + threadIdx.x], tsum);
    }
}

// ---------------- kBN1 ----------------
__global__ void kBN1(const float* __restrict__ g00, const float* __restrict__ b00,
                     const float* __restrict__ g10, const float* __restrict__ b10) {
    int t = threadIdx.x;
    const float invN = 1.f / 655360.f;
    if (t < 32) {
        float m = g_st00[t*2] * invN;
        float v = g_st00[t*2 + 1] * invN - m*m;
        float sc = g00[t] * rsqrtf(v + 1e-5f);
        g_sc00[t] = sc; g_sh00[t] = b00[t] - m*sc;
    } else if (t < 64) {
        int c = t - 32;
        float m = g_st10[c*2] * invN;
        float v = g_st10[c*2 + 1] * invN - m*m;
        float sc = g10[c] * rsqrtf(v + 1e-5f);
        g_sc10[c] = sc; g_sh10[c] = b10[c] - m*sc;
    }
}

// ---------------- kConvMid (scalar FFMA2 path, unchanged) ----------------
__global__ void __launch_bounds__(256, 2) kConvMid(const float* __restrict__ w01) {
    __shared__ float sh[32][6][68];
    __shared__ __align__(16) float2 sw2[32][16][8];
    __shared__ float sstat[64];
    const int tid  = threadIdx.x;
    const int wg   = tid >> 5;
    const int lane = tid & 31;
    const int qr   = lane >> 3;
    const int qc   = lane & 7;
    const int bz   = blockIdx.z;
    const int r0   = blockIdx.y * 4;
    const int cb0  = blockIdx.x * 64;

    if (tid < 64) sstat[tid] = 0.f;

    for (int idx = tid; idx < 32*6*66; idx += 256) {
        int ci = idx / 396, rem = idx % 396;
        int rr = rem / 66, cc = rem % 66;
        float v = 0.f;
        int gc = cb0 - 1 + cc;
        if ((unsigned)gc < WF) {
            int gr = r0 - 1 + rr; gr = (gr + HF) % HF;
            float y = g_y0[(((size_t)bz*CO_ + ci)*HF + gr)*WF + gc];
            v = fmaxf(y * g_sc00[ci] + g_sh00[ci], 0.f);
        }
        sh[ci][rr][cc] = v;
    }
    {
        const int tk[7] = {0, 1, 3, 4, 5, 7, 8};
        for (int idx = tid; idx < 32*16*8; idx += 256) {
            int t7  = idx & 7;
            int cop = (idx >> 3) & 15;
            int ci  = idx >> 7;
            float2 v = make_float2(0.f, 0.f);
            if (t7 < 7) {
                v.x = w01[((2*cop + 0)*CO_ + ci)*9 + tk[t7]];
                v.y = w01[((2*cop + 1)*CO_ + ci)*9 + tk[t7]];
            }
            ((float2*)sw2)[idx] = v;
        }
    }
    __syncthreads();

    u64 acc[2][8];
#pragma unroll
    for (int c = 0; c < 2; c++)
#pragma unroll
        for (int o = 0; o < 8; o++) acc[c][o] = 0ull;

#pragma unroll 2
    for (int ci = 0; ci < CO_; ++ci) {
#pragma unroll
        for (int r = 0; r < 3; r++) {
            float4 t0 = *(const float4*)&sh[ci][qr + r][qc*8];
            float4 t1 = *(const float4*)&sh[ci][qr + r][qc*8 + 4];
            float2 t2 = *(const float2*)&sh[ci][qr + r][qc*8 + 8];
            u64 D[10];
            D[0] = pk2(t0.x, t0.x); D[1] = pk2(t0.y, t0.y);
            D[2] = pk2(t0.z, t0.z); D[3] = pk2(t0.w, t0.w);
            D[4] = pk2(t1.x, t1.x); D[5] = pk2(t1.y, t1.y);
            D[6] = pk2(t1.z, t1.z); D[7] = pk2(t1.w, t1.w);
            D[8] = pk2(t2.x, t2.x); D[9] = pk2(t2.y, t2.y);
            const int tbase = (r == 0) ? 0 : (r == 1) ? 2 : 5;
            const int ntap  = (r == 1) ? 3 : 2;
            const int cof   = (r == 2) ? 1 : 0;
#pragma unroll
            for (int tt = 0; tt < 3; tt++) {
                if (tt < ntap) {
                    const int t  = tbase + tt;
                    const int ct = cof + tt;
#pragma unroll
                    for (int c = 0; c < 2; c++) {
                        u64 w = *(const u64*)&sw2[ci][wg*2 + c][t];
#pragma unroll
                        for (int o = 0; o < 8; o++)
                            fma2(acc[c][o], w, D[ct + o]);
                    }
                }
            }
        }
    }

#pragma unroll
    for (int c = 0; c < 2; c++) {
        float lo[8], hi[8];
#pragma unroll
        for (int o = 0; o < 8; o++) upk2(acc[c][o], lo[o], hi[o]);
        const int coe = (wg*2 + c)*2, coo = coe + 1;
        size_t be = (((size_t)bz*CO_ + coe)*HF + r0 + qr)*WF + cb0 + qc*8;
        size_t bo = (((size_t)bz*CO_ + coo)*HF + r0 + qr)*WF + cb0 + qc*8;
        *(float4*)&g_o0[be]     = make_float4(lo[0], lo[1], lo[2], lo[3]);
        *(float4*)&g_o0[be + 4] = make_float4(lo[4], lo[5], lo[6], lo[7]);
        *(float4*)&g_o0[bo]     = make_float4(hi[0], hi[1], hi[2], hi[3]);
        *(float4*)&g_o0[bo + 4] = make_float4(hi[4], hi[5], hi[6], hi[7]);
        float s1 = 0.f, s2 = 0.f, u1 = 0.f, u2 = 0.f;
#pragma unroll
        for (int o = 0; o < 8; o++) {
            s1 += lo[o]; s2 += lo[o]*lo[o];
            u1 += hi[o]; u2 += hi[o]*hi[o];
        }
        s1 = wsum(s1); s2 = wsum(s2); u1 = wsum(u1); u2 = wsum(u2);
        if (lane == 0) {
            sstat[coe*2] = s1; sstat[coe*2 + 1] = s2;
            sstat[coo*2] = u1; sstat[coo*2 + 1] = u2;
        }
    }
    __syncthreads();
    if (tid < 64) atomicAdd(&g_st01[tid], sstat[tid]);
}

// ---------------- kBN2 ----------------
__global__ void kBN2(const float* __restrict__ g01, const float* __restrict__ b01) {
    int t = threadIdx.x;
    if (t < 32) {
        const float invN = 1.f / 655360.f;
        float m = g_st01[t*2] * invN;
        float v = g_st01[t*2 + 1] * invN - m*m;
        float sc = g01[t] * rsqrtf(v + 1e-5f);
        g_sc01[t] = sc; g_sh01[t] = b01[t] - m*sc;
    }
}

// ---------------- kOut ----------------
__global__ void kOut(float* __restrict__ out) {
    unsigned idx = blockIdx.x * 256u + threadIdx.x;
    if (idx >= (unsigned)(TOTE / 4)) return;
    unsigned e = idx * 4u;
    int c = (int)((e / (HF*WF)) % CO_);
    float s01 = g_sc01[c], h01 = g_sh01[c];
    float s10 = g_sc10[c], h10 = g_sh10[c];
    float4 a  = *(const float4*)&g_o0[e];
    float4 bq = *(const float4*)&g_y1[e];
    float4 r;
    r.x = fmaxf(fmaf(a.x, s01, h01) + fmaf(bq.x, s10, h10), 0.f);
    r.y = fmaxf(fmaf(a.y, s01, h01) + fmaf(bq.y, s10, h10), 0.f);
    r.z = fmaxf(fmaf(a.z, s01, h01) + fmaf(bq.z, s10, h10), 0.f);
    r.w = fmaxf(fmaf(a.w, s01, h01) + fmaf(bq.w, s10, h10), 0.f);
    *(float4*)&out[e] = r;
}

// ---------------- launch ----------------
extern "C" void kernel_launch(void* const* d_in, const int* in_sizes, int n_in,
                              void* d_out, int out_size) {
    const float* x   = (const float*)d_in[0];
    const float* w00 = (const float*)d_in[1];
    const float* w01 = (const float*)d_in[2];
    const float* w10 = (const float*)d_in[3];
    const float* g00 = (const float*)d_in[4];
    const float* b00 = (const float*)d_in[5];
    const float* g01 = (const float*)d_in[6];
    const float* b01 = (const float*)d_in[7];
    const float* g10 = (const float*)d_in[8];
    const float* b10 = (const float*)d_in[9];

    cudaFuncSetAttribute(kConvUpMMA, cudaFuncAttributeMaxDynamicSharedMemorySize, SM_DYN);

    kZero<<<1, 64>>>();
    kPhase2<<<16, 256>>>(w00, w10);
    kZero<<<1, 64>>>();   // shim: keeps the big conv in ncu's profiled slot
    kConvUpMMA<<<dim3(WC/16, HC/8, BB), 256, SM_DYN>>>(x);
    kStats01<<<dim3(64, BB), 256>>>();
    kBN1<<<1, 64>>>(g00, b00, g10, b10);
    kConvMid<<<dim3(WF/64, HF/4, BB), 256>>>(w01);
    kBN2<<<1, 32>>>(g01, b01);
    kOut<<<(TOTE/4 + 255)/256, 256>>>((float*)d_out);
}

// round 17
// speedup vs baseline: 2.1542x; 1.3427x over previous
#include <cuda_runtime.h>
#include <cuda_fp16.h>
#include <stdint.h>

typedef unsigned long long u64;
typedef unsigned int u32;

#define BB   16
#define CI0  64
#define CO_  32
#define HC   160
#define WC   64
#define HF   320
#define WF   128
#define TOTE (BB*CO_*HF*WF)

// ---------------- scratch ----------------
__device__ float g_y0[TOTE];
__device__ float g_y1[TOTE];
__device__ float g_o0[TOTE];
// conv00/10: 16 stages (phase*4+tap) of [64 n][72 k halfs] fp16 (144B rows)
__device__ __align__(16) unsigned char g_B2[16*64*144];
// conv01: 7 taps of [32 n][40 k halfs] fp16 (80B rows)
__device__ __align__(16) unsigned char g_B3[7*32*80];
__device__ float g_st00[64];
__device__ float g_st10[64];
__device__ float g_st01[64];
__device__ float g_sc00[CO_], g_sh00[CO_];
__device__ float g_sc10[CO_], g_sh10[CO_];
__device__ float g_sc01[CO_], g_sh01[CO_];

// ---------------- helpers ----------------
__device__ __forceinline__ float wsum(float v) {
#pragma unroll
    for (int s = 16; s > 0; s >>= 1) v += __shfl_xor_sync(0xffffffffu, v, s);
    return v;
}
__device__ __forceinline__ void cpasync16(void* dst, const void* src) {
    unsigned d = (unsigned)__cvta_generic_to_shared(dst);
    asm volatile("cp.async.ca.shared.global [%0], [%1], 16;" :: "r"(d), "l"(src));
}
#define CP_COMMIT() asm volatile("cp.async.commit_group;" ::: "memory")
#define CP_WAIT0()  asm volatile("cp.async.wait_group 0;" ::: "memory")
__device__ __forceinline__ u32 smem_u32(const void* p) {
    return (u32)__cvta_generic_to_shared(p);
}
__device__ __forceinline__ void ldsm4(u32* r, u32 addr) {
    asm volatile("ldmatrix.sync.aligned.m8n8.x4.shared.b16 {%0,%1,%2,%3}, [%4];"
        : "=r"(r[0]), "=r"(r[1]), "=r"(r[2]), "=r"(r[3]) : "r"(addr));
}
__device__ __forceinline__ void mma16816(float* d, const u32* a, const u32* b) {
    asm volatile("mma.sync.aligned.m16n8k16.row.col.f32.f16.f16.f32 "
        "{%0,%1,%2,%3}, {%4,%5,%6,%7}, {%8,%9}, {%0,%1,%2,%3};"
        : "+f"(d[0]), "+f"(d[1]), "+f"(d[2]), "+f"(d[3])
        : "r"(a[0]), "r"(a[1]), "r"(a[2]), "r"(a[3]), "r"(b[0]), "r"(b[1]));
}

// SMEM layouts
#define SM_AL  25920
#define SM_B   51840
#define SM_DYN (51840 + 147456 + 1024)
#define MID_AL  25920
#define MID_B   51840
#define MID_DYN (51840 + 17920 + 1024)

// ---------------- kZero ----------------
__global__ void kZero() {
    int t = threadIdx.x;
    if (t < 64) { g_st00[t] = 0.f; g_st10[t] = 0.f; g_st01[t] = 0.f; }
}

// ---------------- kPhase2: up-conv phase weights -> fp16 [stage][n][72] -----
__global__ void kPhase2(const float* __restrict__ w00, const float* __restrict__ w10) {
    int t = blockIdx.x * 256 + threadIdx.x;
    if (t >= 4096) return;
    int n = t >> 6, ci = t & 63;
    int conv = n >> 5, co = n & 31;
    const float* w = (conv ? w10 : w00) + ((size_t)co*CI0 + ci)*9;
    float wm[3][3];
#pragma unroll
    for (int ky = 0; ky < 3; ky++)
#pragma unroll
        for (int kx = 0; kx < 3; kx++) wm[ky][kx] = w[ky*3 + kx];
    wm[0][2] = 0.f; wm[2][0] = 0.f;
    float rs[2][2][3];
#pragma unroll
    for (int dx = 0; dx < 3; dx++) {
        rs[0][0][dx] = wm[0][dx];
        rs[0][1][dx] = wm[1][dx] + wm[2][dx];
        rs[1][0][dx] = wm[0][dx] + wm[1][dx];
        rs[1][1][dx] = wm[2][dx];
    }
#pragma unroll
    for (int a = 0; a < 2; a++)
#pragma unroll
        for (int b = 0; b < 2; b++)
#pragma unroll
            for (int u = 0; u < 2; u++)
#pragma unroll
                for (int v = 0; v < 2; v++) {
                    float P;
                    if (b == 0) P = (v == 0) ? rs[a][u][0] : (rs[a][u][1] + rs[a][u][2]);
                    else        P = (v == 0) ? (rs[a][u][0] + rs[a][u][1]) : rs[a][u][2];
                    int stage = (a*2 + b)*4 + u*2 + v;
                    *(unsigned short*)(g_B2 + (size_t)(stage*64 + n)*144 + ci*2) =
                        __half_as_ushort(__float2half_rn(P));
                }
}

// ---------------- kPhase3: conv01 weights -> fp16 [tap][n=co][40] -----------
__global__ void kPhase3(const float* __restrict__ w01) {
    int t = blockIdx.x * 256 + threadIdx.x;
    if (t >= 1024) return;
    int co = t >> 5, ci = t & 31;
    const int tk[7] = {0, 1, 3, 4, 5, 7, 8};
    const float* w = w01 + ((size_t)co*CO_ + ci)*9;
#pragma unroll
    for (int k = 0; k < 7; k++)
        *(unsigned short*)(g_B3 + ((k*32 + co)*40 + ci)*2) =
            __half_as_ushort(__float2half_rn(w[tk[k]]));
}

// ---------------- kConvUpMMA (proven, unchanged) ----------------------------
__global__ void __launch_bounds__(256) kConvUpMMA(const float* __restrict__ x) {
    extern __shared__ char dsm_raw[];
    char* dsm = (char*)(((uintptr_t)dsm_raw + 1023) & ~(uintptr_t)1023);
    const int tid  = threadIdx.x;
    const int w    = tid >> 5;
    const int lane = tid & 31;
    const int i0 = blockIdx.y * 8, j0 = blockIdx.x * 16, bz = blockIdx.z;
    const int mhalf = w & 1;
    const int nb    = (w >> 1) * 16;

    {
        char* dst = dsm + SM_B;
        for (int i = tid; i < 9216; i += 256)
            cpasync16(dst + i*16, (const char*)g_B2 + i*16);
        CP_COMMIT();
    }

    const float* xb = x + (size_t)bz * CI0 * HC * WC;
    char* Ah = dsm;
    char* Al = dsm + SM_AL;
    for (int idx = tid; idx < 11520; idx += 256) {
        int ci = idx / 180, rem = idx % 180;
        int r = rem / 18, c = rem % 18;
        int gr = (i0 - 1 + r + HC) % HC;
        int gc = j0 - 1 + c;
        float v = 0.f;
        if ((unsigned)gc < WC) v = xb[(size_t)ci*HC*WC + (size_t)gr*WC + gc];
        __half h = __float2half_rn(v);
        __half l = __float2half_rn(v - __half2float(h));
        int off = (r*18 + c)*144 + ci*2;
        *(unsigned short*)(Ah + off) = __half_as_ushort(h);
        *(unsigned short*)(Al + off) = __half_as_ushort(l);
    }
    CP_WAIT0();
    __syncthreads();

    const int lj  = lane & 15;
    const int lkb = (lane >> 4) * 16;
    const u32 aH = smem_u32(Ah) + (lj + 1)*144 + lkb;
    const u32 aL = aH + SM_AL;
    const u32 bBase = smem_u32(dsm + SM_B)
        + ((lane & 7) + ((lane >> 4) << 3) + nb)*144 + ((lane >> 3) & 1)*16;

    const int lr = lane >> 2, lc = (lane & 3)*2;

#pragma unroll 1
    for (int mp = 0; mp < 2; ++mp) {
        const int mtb = mhalf*4 + mp*2;
        float acc[4][2][2][4];
#pragma unroll
        for (int p = 0; p < 4; p++)
#pragma unroll
            for (int m2 = 0; m2 < 2; m2++)
#pragma unroll
                for (int nt = 0; nt < 2; nt++)
#pragma unroll
                    for (int e = 0; e < 4; e++) acc[p][m2][nt][e] = 0.f;

#pragma unroll
        for (int s9 = 0; s9 < 9; ++s9) {
            const int sy = s9/3 - 1, sx = s9%3 - 1;
#pragma unroll
            for (int kq = 0; kq < 4; ++kq) {
                const int ro = ((mtb + 1 + sy)*18 + sx)*144 + kq*32;
                u32 Ah0[4], Ah1[4], Al0[4], Al1[4];
                ldsm4(Ah0, (u32)((int)aH + ro));
                ldsm4(Ah1, (u32)((int)aH + ro + 18*144));
                ldsm4(Al0, (u32)((int)aL + ro));
                ldsm4(Al1, (u32)((int)aL + ro + 18*144));
#pragma unroll
                for (int ph = 0; ph < 4; ++ph) {
                    const int a = ph >> 1, bq = ph & 1;
                    const int u = sy + 1 - a, v = sx + 1 - bq;
                    if (u >= 0 && u < 2 && v >= 0 && v < 2) {
                        const int stage = ph*4 + u*2 + v;
                        u32 Bf[4];
                        ldsm4(Bf, bBase + (u32)(stage*64*144 + kq*32));
                        mma16816(acc[ph][0][0], Ah0, Bf);
                        mma16816(acc[ph][0][1], Ah0, Bf + 2);
                        mma16816(acc[ph][1][0], Ah1, Bf);
                        mma16816(acc[ph][1][1], Ah1, Bf + 2);
                        mma16816(acc[ph][0][0], Al0, Bf);
                        mma16816(acc[ph][0][1], Al0, Bf + 2);
                        mma16816(acc[ph][1][0], Al1, Bf);
                        mma16816(acc[ph][1][1], Al1, Bf + 2);
                    }
                }
            }
        }

#pragma unroll
        for (int ph = 0; ph < 4; ++ph) {
            const int a = ph >> 1, bq = ph & 1;
#pragma unroll
            for (int m2 = 0; m2 < 2; ++m2) {
                const int fy = 2*(i0 + mtb + m2) + a;
#pragma unroll
                for (int nt = 0; nt < 2; ++nt) {
                    const int n = nb + nt*8 + lc;
                    float* dst = (n < 32) ? g_y0 : g_y1;
                    const int co = n & 31;
                    size_t rb = (((size_t)bz*CO_ + co)*HF + fy)*(size_t)WF;
                    const int fx1 = 2*(j0 + lr) + bq;
                    dst[rb + fx1]                  = acc[ph][m2][nt][0];
                    dst[rb + (size_t)HF*WF + fx1]  = acc[ph][m2][nt][1];
                    dst[rb + fx1 + 16]             = acc[ph][m2][nt][2];
                    dst[rb + (size_t)HF*WF + fx1 + 16] = acc[ph][m2][nt][3];
                }
            }
        }
    }
}

// ---------------- kConvMidMMA: warp-mma conv01 on h=relu(bn00(y0)) ----------
// grid (8, 20, 16), block 256 (8 warps). Tile 16x16 fine; halo slots [18][18].
// A[m=slot, k=32 ci] fp16 hi/lo (80B rows); B[k=ci, n=co] fp16 per tap.
__global__ void __launch_bounds__(256, 2) kConvMidMMA() {
    extern __shared__ char dsm_raw2[];
    char* dsm = (char*)(((uintptr_t)dsm_raw2 + 1023) & ~(uintptr_t)1023);
    const int tid  = threadIdx.x;
    const int w    = tid >> 5;
    const int lane = tid & 31;
    const int r0 = blockIdx.y * 16, c0 = blockIdx.x * 16, bz = blockIdx.z;

    // stage all 7 weight blocks (17920 B)
    for (int i = tid; i < 1120; i += 256)
        cpasync16(dsm + MID_B + i*16, (const char*)g_B3 + i*16);
    CP_COMMIT();

    // stage A halo tile: bn00+relu, hi/lo fp16, 80B row stride
    char* Ah = dsm;
    char* Al = dsm + MID_AL;
    for (int idx = tid; idx < 10368; idx += 256) {
        int ci = idx / 324, rem = idx % 324;
        int rr = rem / 18, cc = rem % 18;
        int gr = (r0 - 1 + rr + HF) % HF;
        int gc = c0 - 1 + cc;
        float v = 0.f;
        if ((unsigned)gc < WF) {
            float y = g_y0[(((size_t)bz*CO_ + ci)*HF + gr)*WF + gc];
            v = fmaxf(y * g_sc00[ci] + g_sh00[ci], 0.f);
        }
        __half h = __float2half_rn(v);
        __half l = __float2half_rn(v - __half2float(h));
        int off = (rr*18 + cc)*80 + ci*2;
        *(unsigned short*)(Ah + off) = __half_as_ushort(h);
        *(unsigned short*)(Al + off) = __half_as_ushort(l);
    }
    CP_WAIT0();
    __syncthreads();

    const int lj = lane & 15;
    const u32 AhS = smem_u32(Ah), AlS = smem_u32(Al), BS = smem_u32(dsm + MID_B);
    const u32 aLane = (lane >> 4) * 16;
    const u32 bl = (u32)(((lane & 7) + ((lane >> 4) << 3))*80 + ((lane >> 3) & 1)*16);
    const int lr = lane >> 2, lc = (lane & 3)*2;
    const int tapoff[7] = {-19, -18, -1, 0, 1, 18, 19};

#pragma unroll 1
    for (int m2 = 0; m2 < 2; ++m2) {
        const int r = w*2 + m2;
        const u32 arow = (u32)(((r + 1)*18 + 1 + lj)*80) + aLane;
        float acc[4][4];
#pragma unroll
        for (int nf = 0; nf < 4; nf++)
#pragma unroll
            for (int e = 0; e < 4; e++) acc[nf][e] = 0.f;

#pragma unroll
        for (int t = 0; t < 7; ++t) {
            const int to = tapoff[t]*80;
#pragma unroll
            for (int kq = 0; kq < 2; ++kq) {
                u32 ah[4], al[4], b0[4], b1[4];
                ldsm4(ah, (u32)((int)(AhS + arow) + to + kq*32));
                ldsm4(al, (u32)((int)(AlS + arow) + to + kq*32));
                ldsm4(b0, BS + (u32)(t*2560 + kq*32) + bl);
                ldsm4(b1, BS + (u32)(t*2560 + 1280 + kq*32) + bl);
                mma16816(acc[0], ah, b0);
                mma16816(acc[1], ah, b0 + 2);
                mma16816(acc[2], ah, b1);
                mma16816(acc[3], ah, b1 + 2);
                mma16816(acc[0], al, b0);
                mma16816(acc[1], al, b0 + 2);
                mma16816(acc[2], al, b1);
                mma16816(acc[3], al, b1 + 2);
            }
        }

        // epilogue: m = fine col, n = co
        const int rf = r0 + r;
        const int c1 = c0 + lr, c2 = c1 + 8;
#pragma unroll
        for (int nf = 0; nf < 4; ++nf) {
            const int coa = nf*8 + lc;
            size_t ba = (((size_t)bz*CO_ + coa)*HF + rf)*(size_t)WF;
            size_t bb = ba + (size_t)HF*WF;   // coa+1
            g_o0[ba + c1] = acc[nf][0];
            g_o0[bb + c1] = acc[nf][1];
            g_o0[ba + c2] = acc[nf][2];
            g_o0[bb + c2] = acc[nf][3];
        }
    }
}

// ---------------- kStats01: per-channel sums of y0/y1 ----------------------
__global__ void kStats01() {
    __shared__ float ss[16];
    const int cs = blockIdx.x, b = blockIdx.y;
    const float* src = (cs < 32 ? g_y0 : g_y1) + ((size_t)b*CO_ + (cs & 31)) * HF * WF;
    float s1 = 0.f, s2 = 0.f;
    for (int i = threadIdx.x; i < HF*WF/4; i += 256) {
        float4 v = ((const float4*)src)[i];
        s1 += v.x + v.y + v.z + v.w;
        s2 += v.x*v.x + v.y*v.y + v.z*v.z + v.w*v.w;
    }
    s1 = wsum(s1); s2 = wsum(s2);
    int w = threadIdx.x >> 5, l = threadIdx.x & 31;
    if (l == 0) { ss[w*2] = s1; ss[w*2 + 1] = s2; }
    __syncthreads();
    if (threadIdx.x < 2) {
        float tsum = 0.f;
        for (int w2 = 0; w2 < 8; w2++) tsum += ss[w2*2 + threadIdx.x];
        float* st = (cs < 32) ? g_st00 : g_st10;
        atomicAdd(&st[(cs & 31)*2 + threadIdx.x], tsum);
    }
}

// ---------------- kStatsMid: per-channel sums of o0 ------------------------
__global__ void kStatsMid() {
    __shared__ float ss[16];
    const int co = blockIdx.x, b = blockIdx.y;
    const float* src = g_o0 + ((size_t)b*CO_ + co) * HF * WF;
    float s1 = 0.f, s2 = 0.f;
    for (int i = threadIdx.x; i < HF*WF/4; i += 256) {
        float4 v = ((const float4*)src)[i];
        s1 += v.x + v.y + v.z + v.w;
        s2 += v.x*v.x + v.y*v.y + v.z*v.z + v.w*v.w;
    }
    s1 = wsum(s1); s2 = wsum(s2);
    int w = threadIdx.x >> 5, l = threadIdx.x & 31;
    if (l == 0) { ss[w*2] = s1; ss[w*2 + 1] = s2; }
    __syncthreads();
    if (threadIdx.x < 2) {
        float tsum = 0.f;
        for (int w2 = 0; w2 < 8; w2++) tsum += ss[w2*2 + threadIdx.x];
        atomicAdd(&g_st01[co*2 + threadIdx.x], tsum);
    }
}

// ---------------- kBN1 ----------------
__global__ void kBN1(const float* __restrict__ g00, const float* __restrict__ b00,
                     const float* __restrict__ g10, const float* __restrict__ b10) {
    int t = threadIdx.x;
    const float invN = 1.f / 655360.f;
    if (t < 32) {
        float m = g_st00[t*2] * invN;
        float v = g_st00[t*2 + 1] * invN - m*m;
        float sc = g00[t] * rsqrtf(v + 1e-5f);
        g_sc00[t] = sc; g_sh00[t] = b00[t] - m*sc;
    } else if (t < 64) {
        int c = t - 32;
        float m = g_st10[c*2] * invN;
        float v = g_st10[c*2 + 1] * invN - m*m;
        float sc = g10[c] * rsqrtf(v + 1e-5f);
        g_sc10[c] = sc; g_sh10[c] = b10[c] - m*sc;
    }
}

// ---------------- kBN2 ----------------
__global__ void kBN2(const float* __restrict__ g01, const float* __restrict__ b01) {
    int t = threadIdx.x;
    if (t < 32) {
        const float invN = 1.f / 655360.f;
        float m = g_st01[t*2] * invN;
        float v = g_st01[t*2 + 1] * invN - m*m;
        float sc = g01[t] * rsqrtf(v + 1e-5f);
        g_sc01[t] = sc; g_sh01[t] = b01[t] - m*sc;
    }
}

// ---------------- kOut ----------------
__global__ void kOut(float* __restrict__ out) {
    unsigned idx = blockIdx.x * 256u + threadIdx.x;
    if (idx >= (unsigned)(TOTE / 4)) return;
    unsigned e = idx * 4u;
    int c = (int)((e / (HF*WF)) % CO_);
    float s01 = g_sc01[c], h01 = g_sh01[c];
    float s10 = g_sc10[c], h10 = g_sh10[c];
    float4 a  = *(const float4*)&g_o0[e];
    float4 bq = *(const float4*)&g_y1[e];
    float4 r;
    r.x = fmaxf(fmaf(a.x, s01, h01) + fmaf(bq.x, s10, h10), 0.f);
    r.y = fmaxf(fmaf(a.y, s01, h01) + fmaf(bq.y, s10, h10), 0.f);
    r.z = fmaxf(fmaf(a.z, s01, h01) + fmaf(bq.z, s10, h10), 0.f);
    r.w = fmaxf(fmaf(a.w, s01, h01) + fmaf(bq.w, s10, h10), 0.f);
    *(float4*)&out[e] = r;
}

// ---------------- launch ----------------
extern "C" void kernel_launch(void* const* d_in, const int* in_sizes, int n_in,
                              void* d_out, int out_size) {
    const float* x   = (const float*)d_in[0];
    const float* w00 = (const float*)d_in[1];
    const float* w01 = (const float*)d_in[2];
    const float* w10 = (const float*)d_in[3];
    const float* g00 = (const float*)d_in[4];
    const float* b00 = (const float*)d_in[5];
    const float* g01 = (const float*)d_in[6];
    const float* b01 = (const float*)d_in[7];
    const float* g10 = (const float*)d_in[8];
    const float* b10 = (const float*)d_in[9];

    cudaFuncSetAttribute(kConvUpMMA,  cudaFuncAttributeMaxDynamicSharedMemorySize, SM_DYN);
    cudaFuncSetAttribute(kConvMidMMA, cudaFuncAttributeMaxDynamicSharedMemorySize, MID_DYN);

    kZero<<<1, 64>>>();
    kPhase2<<<16, 256>>>(w00, w10);
    kPhase3<<<4, 256>>>(w01);
    kConvUpMMA<<<dim3(WC/16, HC/8, BB), 256, SM_DYN>>>(x);   // launch idx 3 = profiled
    kStats01<<<dim3(64, BB), 256>>>();
    kBN1<<<1, 64>>>(g00, b00, g10, b10);
    kConvMidMMA<<<dim3(WF/16, HF/16, BB), 256, MID_DYN>>>();
    kStatsMid<<<dim3(32, BB), 256>>>();
    kBN2<<<1, 32>>>(g01, b01);
    kOut<<<(TOTE/4 + 255)/256, 256>>>((float*)d_out);
}